// round 1
// baseline (speedup 1.0000x reference)
#include <cuda_runtime.h>
#include <math.h>

#define B_SZ   16384
#define NROWS  2048
#define NCOLS  128
#define CTRL   1024
#define NH     134            // NCOLS + 6
#define EPSV   1e-16f

// ---------------- scratch (device globals; no allocation allowed) ----------
__device__ float g_k[B_SZ * NCOLS];      // controller key k  [B,128]
__device__ float g_prm[B_SZ * 6];        // beta, g, s0,s1,s2, gamma (post-activation)
__device__ float g_mnorm[NROWS];         // ||M_j||

__device__ __forceinline__ float softplusf(float x) {
    return (x > 20.f) ? x : log1pf(expf(x));
}

// ---------------- K0: M row norms ------------------------------------------
__global__ void k0_mnorm(const float* __restrict__ M) {
    int row  = blockIdx.x * 8 + (threadIdx.x >> 5);
    int lane = threadIdx.x & 31;
    const float4* M4 = (const float4*)(M + (size_t)row * NCOLS);
    float4 v = M4[lane];                       // 32 lanes * 4 = 128 elems
    float s = v.x*v.x + v.y*v.y + v.z*v.z + v.w*v.w;
    #pragma unroll
    for (int o = 16; o > 0; o >>= 1) s += __shfl_xor_sync(0xffffffffu, s, o);
    if (lane == 0) g_mnorm[row] = sqrtf(s);
}

// ---------------- K1: h = x@W + b, split into k + activated params ---------
#define BM  128
#define BKK 32

__global__ __launch_bounds__(256)
void k1_gemm(const float* __restrict__ x, const float* __restrict__ W,
             const float* __restrict__ bfc) {
    __shared__ float As[BKK][132];     // x tile, transposed, padded
    __shared__ float Bs[BKK][128];     // W[:, :128] tile
    __shared__ float Ps[BKK][6];       // W[:, 128:134] tile
    __shared__ float hp[BM][6];        // raw param pre-activations

    int tid  = threadIdx.x;
    int row0 = blockIdx.x * BM;
    int tr   = tid >> 4;               // 0..15
    int tc   = tid & 15;               // 0..15
    int mp   = tid & 127;              // param row
    int cg   = tid >> 7;               // param col-group (0/1 -> cols 0..2 / 3..5)

    float acc[8][8];
    #pragma unroll
    for (int i = 0; i < 8; i++)
        #pragma unroll
        for (int j = 0; j < 8; j++) acc[i][j] = 0.f;
    float acc3[3] = {0.f, 0.f, 0.f};

    for (int kt = 0; kt < CTRL; kt += BKK) {
        // load x tile (float4, coalesced) -> As[k][m]
        #pragma unroll
        for (int u = 0; u < 4; u++) {
            int fid = tid + u * 256;
            int m = fid >> 3, kq = fid & 7;
            float4 v = *(const float4*)(x + (size_t)(row0 + m) * CTRL + kt + kq * 4);
            As[kq*4+0][m] = v.x; As[kq*4+1][m] = v.y;
            As[kq*4+2][m] = v.z; As[kq*4+3][m] = v.w;
        }
        // load W tile (scalar; row stride 134 breaks float4 alignment)
        #pragma unroll
        for (int u = 0; u < 16; u++) {
            int id = tid + u * 256;
            int k = id >> 7, n = id & 127;
            Bs[k][n] = W[(size_t)(kt + k) * NH + n];
        }
        if (tid < BKK * 6) {
            int k = tid / 6, c = tid % 6;
            Ps[k][c] = W[(size_t)(kt + k) * NH + 128 + c];
        }
        __syncthreads();

        #pragma unroll 4
        for (int kk = 0; kk < BKK; kk++) {
            float4 a0 = *(const float4*)&As[kk][tr*8];
            float4 a1 = *(const float4*)&As[kk][tr*8 + 4];
            float4 b0 = *(const float4*)&Bs[kk][tc*8];
            float4 b1 = *(const float4*)&Bs[kk][tc*8 + 4];
            float a[8] = {a0.x,a0.y,a0.z,a0.w,a1.x,a1.y,a1.z,a1.w};
            float b[8] = {b0.x,b0.y,b0.z,b0.w,b1.x,b1.y,b1.z,b1.w};
            #pragma unroll
            for (int i = 0; i < 8; i++)
                #pragma unroll
                for (int j = 0; j < 8; j++)
                    acc[i][j] = fmaf(a[i], b[j], acc[i][j]);
            float xv = As[kk][mp];
            #pragma unroll
            for (int c = 0; c < 3; c++)
                acc3[c] = fmaf(xv, Ps[kk][cg*3 + c], acc3[c]);
        }
        __syncthreads();
    }

    // k epilogue (+bias), float4 stores
    float bj[8];
    #pragma unroll
    for (int j = 0; j < 8; j++) bj[j] = bfc[tc*8 + j];
    #pragma unroll
    for (int i = 0; i < 8; i++) {
        int gr = row0 + tr*8 + i;
        float4 o0 = make_float4(acc[i][0]+bj[0], acc[i][1]+bj[1],
                                acc[i][2]+bj[2], acc[i][3]+bj[3]);
        float4 o1 = make_float4(acc[i][4]+bj[4], acc[i][5]+bj[5],
                                acc[i][6]+bj[6], acc[i][7]+bj[7]);
        *(float4*)(g_k + (size_t)gr * NCOLS + tc*8)     = o0;
        *(float4*)(g_k + (size_t)gr * NCOLS + tc*8 + 4) = o1;
    }

    // param epilogue
    #pragma unroll
    for (int c = 0; c < 3; c++)
        hp[mp][cg*3 + c] = acc3[c] + bfc[128 + cg*3 + c];
    __syncthreads();
    if (tid < BM) {
        float h0 = hp[tid][0], h1 = hp[tid][1], h2 = hp[tid][2];
        float h3 = hp[tid][3], h4 = hp[tid][4], h5 = hp[tid][5];
        float beta  = softplusf(h0);
        float g     = 1.f / (1.f + expf(-h1));
        float m3    = fmaxf(h2, fmaxf(h3, h4));
        float e0 = expf(h2 - m3), e1 = expf(h3 - m3), e2 = expf(h4 - m3);
        float inv = 1.f / (e0 + e1 + e2);
        float gamma = 1.f + softplusf(h5);
        size_t gr = (size_t)(row0 + tid) * 6;
        g_prm[gr+0] = beta;  g_prm[gr+1] = g;
        g_prm[gr+2] = e0*inv; g_prm[gr+3] = e1*inv; g_prm[gr+4] = e2*inv;
        g_prm[gr+5] = gamma;
    }
}

// ---------------- K2: fused addressing + read ------------------------------
#define RPB 16
#define K2T 512
// smem floats: wbuf 16*2048 | ks 16*128 | scratch 4*16*128 | prm 16*8 | kn 16 | ips 16
#define K2_SMEM_FLOATS (RPB*NROWS + RPB*NCOLS + 4*RPB*NCOLS + RPB*8 + RPB + RPB)
#define K2_SMEM_BYTES  (K2_SMEM_FLOATS * 4)

__global__ __launch_bounds__(K2T)
void k2_fused(const float* __restrict__ M, const float* __restrict__ wprev,
              float* __restrict__ out) {
    extern __shared__ float smf[];
    float* wbuf    = smf;                          // [16][2048]
    float* ks      = wbuf + RPB*NROWS;             // [16][128]
    float* scratch = ks + RPB*NCOLS;               // [4][16][128]
    float* prm     = scratch + 4*RPB*NCOLS;        // [16][8]
    float* kn      = prm + RPB*8;                  // [16]
    float* ips     = kn + RPB;                     // [16]

    int tid  = threadIdx.x;
    int lane = tid & 31;
    int wid  = tid >> 5;                           // 0..15, one warp per row
    int row0 = blockIdx.x * RPB;

    // load k rows + params
    {
        int r = tid >> 5;
        float4 v = *(const float4*)(g_k + (size_t)(row0 + r) * NCOLS + lane*4);
        *(float4*)&ks[r*NCOLS + lane*4] = v;
    }
    if (tid < RPB*6) {
        int r = tid / 6, c = tid % 6;
        prm[r*8 + c] = g_prm[(size_t)(row0 + r) * 6 + c];
    }
    __syncthreads();

    // k norms: warp wid -> row wid
    {
        float s = 0.f;
        #pragma unroll
        for (int u = 0; u < 4; u++) {
            float v = ks[wid*NCOLS + lane + 32*u];
            s += v * v;
        }
        #pragma unroll
        for (int o = 16; o > 0; o >>= 1) s += __shfl_xor_sync(0xffffffffu, s, o);
        if (lane == 0) kn[wid] = sqrtf(s);
    }
    __syncthreads();

    // ---- sim + scaled logits into wbuf ----
    #pragma unroll
    for (int jt = 0; jt < NROWS; jt += K2T) {
        int j = jt + tid;
        const float4* Mr = (const float4*)(M + (size_t)j * NCOLS);
        float acc[RPB];
        #pragma unroll
        for (int r = 0; r < RPB; r++) acc[r] = 0.f;
        #pragma unroll 4
        for (int i4 = 0; i4 < 32; i4++) {
            float4 mv = __ldg(Mr + i4);
            #pragma unroll
            for (int r = 0; r < RPB; r++) {
                float4 kv = *(const float4*)&ks[r*NCOLS + i4*4];
                acc[r] += kv.x*mv.x + kv.y*mv.y + kv.z*mv.z + kv.w*mv.w;
            }
        }
        float mn = g_mnorm[j];
        #pragma unroll
        for (int r = 0; r < RPB; r++) {
            float denom = kn[r] * mn + EPSV;
            wbuf[r*NROWS + j] = prm[r*8 + 0] * acc[r] / denom;
        }
    }
    __syncthreads();

    // ---- per-warp row pipeline: softmax -> blend -> shift -> pow ----
    {
        int r = wid;
        float* wr = wbuf + r*NROWS;
        float g  = prm[r*8+1], s0 = prm[r*8+2], s1 = prm[r*8+3];
        float s2 = prm[r*8+4], gm = prm[r*8+5];

        float mx = -1e30f;
        for (int u = 0; u < 64; u++) mx = fmaxf(mx, wr[lane + 32*u]);
        #pragma unroll
        for (int o = 16; o > 0; o >>= 1) mx = fmaxf(mx, __shfl_xor_sync(0xffffffffu, mx, o));

        float sum = 0.f;
        for (int u = 0; u < 64; u++) {
            int idx = lane + 32*u;
            float e = __expf(wr[idx] - mx);
            wr[idx] = e;
            sum += e;
        }
        #pragma unroll
        for (int o = 16; o > 0; o >>= 1) sum += __shfl_xor_sync(0xffffffffu, sum, o);

        float gc = g / sum, og = 1.f - g;
        const float* wp = wprev + (size_t)(row0 + r) * NROWS;
        for (int u = 0; u < 64; u++) {
            int idx = lane + 32*u;
            wr[idx] = gc * wr[idx] + og * __ldg(wp + idx);
        }
        __syncwarp();

        // circular shift + sharpen, in-place with lane-31 carry
        float w0    = wr[0];
        float carry = wr[NROWS - 1];
        float psum  = 0.f;
        for (int ch = 0; ch < 64; ch++) {
            int j = ch*32 + lane;
            float c0  = wr[j];
            float lft = (lane == 0)      ? carry : wr[j-1];
            float rgt = (j == NROWS - 1) ? w0    : wr[j+1];
            float t = s0*lft + s1*c0 + s2*rgt + EPSV;
            float p = __powf(t, gm);
            __syncwarp();
            wr[j] = p;
            carry = __shfl_sync(0xffffffffu, c0, 31);
            psum += p;
            __syncwarp();
        }
        #pragma unroll
        for (int o = 16; o > 0; o >>= 1) psum += __shfl_xor_sync(0xffffffffu, psum, o);
        if (lane == 0) ips[r] = 1.f / psum;
    }
    __syncthreads();

    // ---- r = w @ M ----
    {
        int c = tid & 127, q = tid >> 7;     // 4 j-quarters
        float acc[RPB];
        #pragma unroll
        for (int r = 0; r < RPB; r++) acc[r] = 0.f;
        int jb = q * (NROWS/4);
        for (int j = jb; j < jb + NROWS/4; j += 2) {
            float m0 = __ldg(M + (size_t)j * NCOLS + c);
            float m1 = __ldg(M + (size_t)(j+1) * NCOLS + c);
            #pragma unroll
            for (int r = 0; r < RPB; r++) {
                float2 p = *(const float2*)&wbuf[r*NROWS + j];
                acc[r] += p.x*m0 + p.y*m1;
            }
        }
        #pragma unroll
        for (int r = 0; r < RPB; r++)
            scratch[(q*RPB + r)*NCOLS + c] = acc[r];
    }
    __syncthreads();
    #pragma unroll
    for (int u = 0; u < 4; u++) {
        int idx = tid + u * K2T;
        int r = idx >> 7, c = idx & 127;
        float v = scratch[(0*RPB + r)*NCOLS + c] + scratch[(1*RPB + r)*NCOLS + c]
                + scratch[(2*RPB + r)*NCOLS + c] + scratch[(3*RPB + r)*NCOLS + c];
        out[(size_t)(row0 + r) * NCOLS + c] = v * ips[r];
    }
}

// ---------------- launch ----------------------------------------------------
extern "C" void kernel_launch(void* const* d_in, const int* in_sizes, int n_in,
                              void* d_out, int out_size) {
    // defensive remap by element count (all five sizes distinct)
    const float *x = 0, *W = 0, *b = 0, *M = 0, *wprev = 0;
    for (int i = 0; i < n_in; i++) {
        switch (in_sizes[i]) {
            case B_SZ * CTRL:   x     = (const float*)d_in[i]; break;   // 16777216
            case CTRL * NH:     W     = (const float*)d_in[i]; break;   // 137216
            case NH:            b     = (const float*)d_in[i]; break;   // 134
            case NROWS * NCOLS: M     = (const float*)d_in[i]; break;   // 262144
            case B_SZ * NROWS:  wprev = (const float*)d_in[i]; break;   // 33554432
        }
    }
    float* out = (float*)d_out;

    cudaFuncSetAttribute(k2_fused, cudaFuncAttributeMaxDynamicSharedMemorySize,
                         K2_SMEM_BYTES);

    k0_mnorm<<<NROWS/8, 256>>>(M);
    k1_gemm<<<B_SZ/BM, 256>>>(x, W, b);
    k2_fused<<<B_SZ/RPB, K2T, K2_SMEM_BYTES>>>(M, wprev, out);
}

// round 2
// speedup vs baseline: 1.0568x; 1.0568x over previous
#include <cuda_runtime.h>
#include <math.h>

#define B_SZ   16384
#define NROWS  2048
#define NCOLS  128
#define CTRL   1024
#define NH     134            // NCOLS + 6
#define EPSV   1e-16f

// ---------------- scratch (device globals; no allocation allowed) ----------
__device__ float g_k[B_SZ * NCOLS];      // controller key k  [B,128]
__device__ float g_prm[B_SZ * 6];        // beta, g, s0,s1,s2, gamma (post-activation)
__device__ float g_mnorm[NROWS];         // ||M_j||

__device__ __forceinline__ float softplusf(float x) {
    return (x > 20.f) ? x : log1pf(expf(x));
}

// ---- fast transcendentals on the FMA pipe (no MUFU) -----------------------
__device__ __forceinline__ float fast_exp2f(float y) {
    y = fminf(fmaxf(y, -125.f), 126.f);
    float r = y + 12582912.f;                  // round-to-nearest-int magic
    int   n = __float_as_int(r) - 0x4B400000;
    float f = y - (r - 12582912.f);            // f in [-0.5, 0.5]
    float p = 1.54035304e-4f;                  // Taylor/minimax exp2, deg 6
    p = fmaf(p, f, 1.33335581e-3f);
    p = fmaf(p, f, 9.61812911e-3f);
    p = fmaf(p, f, 5.55041087e-2f);
    p = fmaf(p, f, 2.40226507e-1f);
    p = fmaf(p, f, 6.93147183e-1f);
    p = fmaf(p, f, 1.0f);
    return __int_as_float(__float_as_int(p) + (n << 23));
}

__device__ __forceinline__ float fast_expf(float x) {
    return fast_exp2f(x * 1.442695041f);
}

// log2 for x > 0 (normal). m reduced to [2/3, 4/3), deg-5 log1p poly.
__device__ __forceinline__ float fast_log2f(float x) {
    int   ib = __float_as_int(x);
    int   e  = (ib - 0x3f2aaaab) & 0xff800000;
    float m  = __int_as_float(ib - e);
    float le = (float)(e >> 23);               // signed exponent
    float f  = m - 1.0f;                       // f in [-1/3, 1/3]
    float s  = f * f;
    float r  = fmaf(0.230836749f, f, -0.279208571f);
    float t  = fmaf(0.331826031f, f, -0.498910338f);
    r = fmaf(r, s, t);
    r = fmaf(r, s, f);                         // ln(1+f)
    return fmaf(r, 1.442695041f, le);
}

__device__ __forceinline__ float fast_powf(float x, float g) {
    return fast_exp2f(g * fast_log2f(x));
}

// ---------------- K0: M row norms ------------------------------------------
__global__ void k0_mnorm(const float* __restrict__ M) {
    int row  = blockIdx.x * 8 + (threadIdx.x >> 5);
    int lane = threadIdx.x & 31;
    const float4* M4 = (const float4*)(M + (size_t)row * NCOLS);
    float4 v = M4[lane];
    float s = v.x*v.x + v.y*v.y + v.z*v.z + v.w*v.w;
    #pragma unroll
    for (int o = 16; o > 0; o >>= 1) s += __shfl_xor_sync(0xffffffffu, s, o);
    if (lane == 0) g_mnorm[row] = sqrtf(s);
}

// ---------------- K1: h = x@W + b, split into k + activated params ---------
#define BM  128
#define BKK 32

__global__ __launch_bounds__(256)
void k1_gemm(const float* __restrict__ x, const float* __restrict__ W,
             const float* __restrict__ bfc) {
    __shared__ float As[BKK][132];
    __shared__ float Bs[BKK][128];
    __shared__ float Ps[BKK][6];
    __shared__ float hp[BM][6];

    int tid  = threadIdx.x;
    int row0 = blockIdx.x * BM;
    int tr   = tid >> 4;
    int tc   = tid & 15;
    int mp   = tid & 127;
    int cg   = tid >> 7;

    float acc[8][8];
    #pragma unroll
    for (int i = 0; i < 8; i++)
        #pragma unroll
        for (int j = 0; j < 8; j++) acc[i][j] = 0.f;
    float acc3[3] = {0.f, 0.f, 0.f};

    for (int kt = 0; kt < CTRL; kt += BKK) {
        #pragma unroll
        for (int u = 0; u < 4; u++) {
            int fid = tid + u * 256;
            int m = fid >> 3, kq = fid & 7;
            float4 v = *(const float4*)(x + (size_t)(row0 + m) * CTRL + kt + kq * 4);
            As[kq*4+0][m] = v.x; As[kq*4+1][m] = v.y;
            As[kq*4+2][m] = v.z; As[kq*4+3][m] = v.w;
        }
        #pragma unroll
        for (int u = 0; u < 16; u++) {
            int id = tid + u * 256;
            int k = id >> 7, n = id & 127;
            Bs[k][n] = W[(size_t)(kt + k) * NH + n];
        }
        if (tid < BKK * 6) {
            int k = tid / 6, c = tid % 6;
            Ps[k][c] = W[(size_t)(kt + k) * NH + 128 + c];
        }
        __syncthreads();

        #pragma unroll 4
        for (int kk = 0; kk < BKK; kk++) {
            float4 a0 = *(const float4*)&As[kk][tr*8];
            float4 a1 = *(const float4*)&As[kk][tr*8 + 4];
            float4 b0 = *(const float4*)&Bs[kk][tc*8];
            float4 b1 = *(const float4*)&Bs[kk][tc*8 + 4];
            float a[8] = {a0.x,a0.y,a0.z,a0.w,a1.x,a1.y,a1.z,a1.w};
            float b[8] = {b0.x,b0.y,b0.z,b0.w,b1.x,b1.y,b1.z,b1.w};
            #pragma unroll
            for (int i = 0; i < 8; i++)
                #pragma unroll
                for (int j = 0; j < 8; j++)
                    acc[i][j] = fmaf(a[i], b[j], acc[i][j]);
            float xv = As[kk][mp];
            #pragma unroll
            for (int c = 0; c < 3; c++)
                acc3[c] = fmaf(xv, Ps[kk][cg*3 + c], acc3[c]);
        }
        __syncthreads();
    }

    float bj[8];
    #pragma unroll
    for (int j = 0; j < 8; j++) bj[j] = bfc[tc*8 + j];
    #pragma unroll
    for (int i = 0; i < 8; i++) {
        int gr = row0 + tr*8 + i;
        float4 o0 = make_float4(acc[i][0]+bj[0], acc[i][1]+bj[1],
                                acc[i][2]+bj[2], acc[i][3]+bj[3]);
        float4 o1 = make_float4(acc[i][4]+bj[4], acc[i][5]+bj[5],
                                acc[i][6]+bj[6], acc[i][7]+bj[7]);
        *(float4*)(g_k + (size_t)gr * NCOLS + tc*8)     = o0;
        *(float4*)(g_k + (size_t)gr * NCOLS + tc*8 + 4) = o1;
    }

    #pragma unroll
    for (int c = 0; c < 3; c++)
        hp[mp][cg*3 + c] = acc3[c] + bfc[128 + cg*3 + c];
    __syncthreads();
    if (tid < BM) {
        float h0 = hp[tid][0], h1 = hp[tid][1], h2 = hp[tid][2];
        float h3 = hp[tid][3], h4 = hp[tid][4], h5 = hp[tid][5];
        float beta  = softplusf(h0);
        float g     = 1.f / (1.f + expf(-h1));
        float m3    = fmaxf(h2, fmaxf(h3, h4));
        float e0 = expf(h2 - m3), e1 = expf(h3 - m3), e2 = expf(h4 - m3);
        float inv = 1.f / (e0 + e1 + e2);
        float gamma = 1.f + softplusf(h5);
        size_t gr = (size_t)(row0 + tid) * 6;
        g_prm[gr+0] = beta;  g_prm[gr+1] = g;
        g_prm[gr+2] = e0*inv; g_prm[gr+3] = e1*inv; g_prm[gr+4] = e2*inv;
        g_prm[gr+5] = gamma;
    }
}

// ---------------- K2: fused addressing + read ------------------------------
#define RPB 16
#define K2T 512
#define NJQ 8                      // j-quarters in read GEMM
// smem floats: wbuf 16*2048 | ks 16*128 | scratch 8*16*128 | prm 16*8 | kn 16 | ips 16
#define K2_SMEM_FLOATS (RPB*NROWS + RPB*NCOLS + NJQ*RPB*NCOLS + RPB*8 + RPB + RPB)
#define K2_SMEM_BYTES  (K2_SMEM_FLOATS * 4)

__global__ __launch_bounds__(K2T)
void k2_fused(const float* __restrict__ M, const float* __restrict__ wprev,
              float* __restrict__ out) {
    extern __shared__ float smf[];
    float* wbuf    = smf;                          // [16][2048]
    float* ks      = wbuf + RPB*NROWS;             // [16][128]
    float* scratch = ks + RPB*NCOLS;               // [8][16][128]
    float* prm     = scratch + NJQ*RPB*NCOLS;      // [16][8]
    float* kn      = prm + RPB*8;                  // [16]
    float* ips     = kn + RPB;                     // [16]

    int tid  = threadIdx.x;
    int lane = tid & 31;
    int wid  = tid >> 5;                           // 0..15, one warp per row
    int row0 = blockIdx.x * RPB;

    // load k rows + params
    {
        int r = tid >> 5;
        float4 v = *(const float4*)(g_k + (size_t)(row0 + r) * NCOLS + lane*4);
        *(float4*)&ks[r*NCOLS + lane*4] = v;
    }
    if (tid < RPB*6) {
        int r = tid / 6, c = tid % 6;
        prm[r*8 + c] = g_prm[(size_t)(row0 + r) * 6 + c];
    }
    __syncthreads();

    // k norms: warp wid -> row wid
    {
        float s = 0.f;
        #pragma unroll
        for (int u = 0; u < 4; u++) {
            float v = ks[wid*NCOLS + lane + 32*u];
            s += v * v;
        }
        #pragma unroll
        for (int o = 16; o > 0; o >>= 1) s += __shfl_xor_sync(0xffffffffu, s, o);
        if (lane == 0) kn[wid] = sqrtf(s);
    }
    __syncthreads();

    // ---- sim + scaled logits into wbuf ----
    #pragma unroll
    for (int jt = 0; jt < NROWS; jt += K2T) {
        int j = jt + tid;
        const float4* Mr = (const float4*)(M + (size_t)j * NCOLS);
        float acc[RPB];
        #pragma unroll
        for (int r = 0; r < RPB; r++) acc[r] = 0.f;
        #pragma unroll 4
        for (int i4 = 0; i4 < 32; i4++) {
            float4 mv = __ldg(Mr + i4);
            #pragma unroll
            for (int r = 0; r < RPB; r++) {
                float4 kv = *(const float4*)&ks[r*NCOLS + i4*4];
                acc[r] += kv.x*mv.x + kv.y*mv.y + kv.z*mv.z + kv.w*mv.w;
            }
        }
        float mn = g_mnorm[j];
        #pragma unroll
        for (int r = 0; r < RPB; r++) {
            float denom = kn[r] * mn + EPSV;
            wbuf[r*NROWS + j] = prm[r*8 + 0] * acc[r] / denom;
        }
    }
    __syncthreads();

    // ---- per-warp row pipeline: softmax -> blend -> shift -> pow ----
    {
        int r = wid;
        float* wr = wbuf + r*NROWS;
        float g  = prm[r*8+1], s0 = prm[r*8+2], s1 = prm[r*8+3];
        float s2 = prm[r*8+4], gm = prm[r*8+5];

        float mx = -1e30f;
        for (int u = 0; u < 64; u++) mx = fmaxf(mx, wr[lane + 32*u]);
        #pragma unroll
        for (int o = 16; o > 0; o >>= 1) mx = fmaxf(mx, __shfl_xor_sync(0xffffffffu, mx, o));

        float sum = 0.f;
        for (int u = 0; u < 64; u++) {
            int idx = lane + 32*u;
            float e = fast_expf(wr[idx] - mx);
            wr[idx] = e;
            sum += e;
        }
        #pragma unroll
        for (int o = 16; o > 0; o >>= 1) sum += __shfl_xor_sync(0xffffffffu, sum, o);

        float gc = g / sum, og = 1.f - g;
        const float* wp = wprev + (size_t)(row0 + r) * NROWS;
        for (int u = 0; u < 64; u++) {
            int idx = lane + 32*u;
            wr[idx] = gc * wr[idx] + og * __ldg(wp + idx);
        }
        __syncwarp();

        // circular shift + sharpen, in-place with lane-31 carry
        float w0    = wr[0];
        float carry = wr[NROWS - 1];
        float psum  = 0.f;
        for (int ch = 0; ch < 64; ch++) {
            int j = ch*32 + lane;
            float c0  = wr[j];
            float lft = (lane == 0)      ? carry : wr[j-1];
            float rgt = (j == NROWS - 1) ? w0    : wr[j+1];
            float t = s0*lft + s1*c0 + s2*rgt + EPSV;
            float p = fast_powf(t, gm);
            __syncwarp();
            wr[j] = p;
            carry = __shfl_sync(0xffffffffu, c0, 31);
            psum += p;
            __syncwarp();
        }
        #pragma unroll
        for (int o = 16; o > 0; o >>= 1) psum += __shfl_xor_sync(0xffffffffu, psum, o);
        if (lane == 0) ips[r] = 1.f / psum;
    }
    __syncthreads();

    // ---- r = w @ M : 8-row x 4-col register tiles, broadcast LDS ----
    {
        int cg = tid & 31;              // column group: c = cg*4
        int rg = (tid >> 5) & 1;        // row group: r0 = rg*8
        int jq = tid >> 6;              // 0..7, 256 j each
        int r0 = rg * 8;
        int jb = jq * (NROWS / NJQ);

        float acc[8][4];
        #pragma unroll
        for (int i = 0; i < 8; i++)
            #pragma unroll
            for (int c = 0; c < 4; c++) acc[i][c] = 0.f;

        #pragma unroll 4
        for (int j = jb; j < jb + NROWS/NJQ; j++) {
            float4 mv = __ldg((const float4*)(M + (size_t)j * NCOLS) + cg);
            #pragma unroll
            for (int i = 0; i < 8; i++) {
                float wv = wbuf[(r0 + i)*NROWS + j];   // warp-broadcast
                acc[i][0] = fmaf(wv, mv.x, acc[i][0]);
                acc[i][1] = fmaf(wv, mv.y, acc[i][1]);
                acc[i][2] = fmaf(wv, mv.z, acc[i][2]);
                acc[i][3] = fmaf(wv, mv.w, acc[i][3]);
            }
        }
        #pragma unroll
        for (int i = 0; i < 8; i++) {
            float4 o = make_float4(acc[i][0], acc[i][1], acc[i][2], acc[i][3]);
            *(float4*)&scratch[((size_t)jq*RPB + r0 + i)*NCOLS + cg*4] = o;
        }
    }
    __syncthreads();
    #pragma unroll
    for (int u = 0; u < 4; u++) {
        int idx = tid + u * K2T;
        int r = idx >> 7, c = idx & 127;
        float v = 0.f;
        #pragma unroll
        for (int q = 0; q < NJQ; q++)
            v += scratch[(q*RPB + r)*NCOLS + c];
        out[(size_t)(row0 + r) * NCOLS + c] = v * ips[r];
    }
}

// ---------------- launch ----------------------------------------------------
extern "C" void kernel_launch(void* const* d_in, const int* in_sizes, int n_in,
                              void* d_out, int out_size) {
    const float *x = 0, *W = 0, *b = 0, *M = 0, *wprev = 0;
    for (int i = 0; i < n_in; i++) {
        switch (in_sizes[i]) {
            case B_SZ * CTRL:   x     = (const float*)d_in[i]; break;
            case CTRL * NH:     W     = (const float*)d_in[i]; break;
            case NH:            b     = (const float*)d_in[i]; break;
            case NROWS * NCOLS: M     = (const float*)d_in[i]; break;
            case B_SZ * NROWS:  wprev = (const float*)d_in[i]; break;
        }
    }
    float* out = (float*)d_out;

    cudaFuncSetAttribute(k2_fused, cudaFuncAttributeMaxDynamicSharedMemorySize,
                         K2_SMEM_BYTES);

    k0_mnorm<<<NROWS/8, 256>>>(M);
    k1_gemm<<<B_SZ/BM, 256>>>(x, W, b);
    k2_fused<<<B_SZ/RPB, K2T, K2_SMEM_BYTES>>>(M, wprev, out);
}